// round 1
// baseline (speedup 1.0000x reference)
#include <cuda_runtime.h>

#define W_BIT 4
#define OUT_F 11008
#define IN_F 4096
#define KRANK 16
#define TOKENS 2048
#define NBYTES (OUT_F * IN_F / 8)

// Scratch for reconstructed weight w[OUT_F][IN_F] (fp32, row-major).
// 11008*4096*4 = ~180 MB, static device global (allocation-free rule).
__device__ float g_w[(size_t)OUT_F * (size_t)IN_F];

// ---------------------------------------------------------------------------
// Kernel 1: reconstruct w[o][i] = sum_b sign_b[o,i] * (u_b[o,:] . vt_b[:,i])
// Bit j of byte m (= flattened (o*IN_F+i)/8) -> element m*8+j; bit 1 -> +1.
// Block: 256 threads covering a [32 o x 128 i] tile. vt working set per block
// is 64 rows x 128 i x 4B = 32 KB -> L1-resident; u row cached in registers.
// ---------------------------------------------------------------------------
__global__ __launch_bounds__(256) void reconstruct_kernel(
    const int* __restrict__ qweight,
    const float* __restrict__ u,
    const float* __restrict__ vt) {
  const int tid = threadIdx.x;
  const int o_local = tid >> 3;  // 0..31
  const int g = tid & 7;         // 0..7
  const int o = blockIdx.y * 32 + o_local;
  const int i_base = blockIdx.x * 128;

  // Cache this thread's u row: u[b][o][k], m = b*16+k.
  float u_r[64];
#pragma unroll
  for (int b = 0; b < W_BIT; b++) {
#pragma unroll
    for (int k = 0; k < KRANK; k++) {
      u_r[b * KRANK + k] = u[((size_t)b * OUT_F + o) * KRANK + k];
    }
  }

#pragma unroll
  for (int gg = 0; gg < 2; gg++) {
    const int i0 = i_base + (g + gg * 8) * 8;  // 8 consecutive i (one byte)
    float acc[8];
#pragma unroll
    for (int j = 0; j < 8; j++) acc[j] = 0.0f;

#pragma unroll
    for (int b = 0; b < W_BIT; b++) {
      const unsigned byte =
          (unsigned)qweight[b * NBYTES + o * (IN_F / 8) + (i0 >> 3)];
      float tmp[8];
#pragma unroll
      for (int j = 0; j < 8; j++) tmp[j] = 0.0f;
#pragma unroll
      for (int k = 0; k < KRANK; k++) {
        const float uv = u_r[b * KRANK + k];
        const float4 v0 =
            *(const float4*)(vt + ((b * KRANK + k) * IN_F + i0));
        const float4 v1 =
            *(const float4*)(vt + ((b * KRANK + k) * IN_F + i0 + 4));
        tmp[0] += uv * v0.x; tmp[1] += uv * v0.y;
        tmp[2] += uv * v0.z; tmp[3] += uv * v0.w;
        tmp[4] += uv * v1.x; tmp[5] += uv * v1.y;
        tmp[6] += uv * v1.z; tmp[7] += uv * v1.w;
      }
#pragma unroll
      for (int j = 0; j < 8; j++) {
        acc[j] += ((byte >> j) & 1u) ? tmp[j] : -tmp[j];
      }
    }

    float4* outp = (float4*)(g_w + (size_t)o * IN_F + i0);
    outp[0] = make_float4(acc[0], acc[1], acc[2], acc[3]);
    outp[1] = make_float4(acc[4], acc[5], acc[6], acc[7]);
  }
}

// ---------------------------------------------------------------------------
// Kernel 2: y[T, O] = x[T, I] @ w[O, I]^T   (fp32 SIMT SGEMM)
// 128x128 CTA tile, BK=16, 256 threads, 8x8 register microtile,
// register prefetch of the next gmem tile overlapped with compute.
// ---------------------------------------------------------------------------
#define BM 128
#define BN 128
#define BK 16
#define SPAD 4

__global__ __launch_bounds__(256, 2) void sgemm_kernel(
    const float* __restrict__ A,  // x [TOKENS][IN_F]
    float* __restrict__ C) {      // y [TOKENS][OUT_F]
  __shared__ __align__(16) float As[BK][BM + SPAD];
  __shared__ __align__(16) float Bs[BK][BN + SPAD];

  const float* B = g_w;  // [OUT_F][IN_F], contiguous along k=i

  const int tid = threadIdx.x;
  const int tx = tid & 15;   // 0..15 -> n microtile
  const int ty = tid >> 4;   // 0..15 -> m microtile
  const int m0 = blockIdx.y * BM;
  const int n0 = blockIdx.x * BN;

  // Tile load mapping: 512 float4 per tile per operand; 2 per thread.
  const int r0 = tid >> 2;          // rows 0..63
  const int r1 = (tid + 256) >> 2;  // rows 64..127
  const int c0 = (tid & 3) << 2;    // k-offset within BK: 0,4,8,12

  const float* Ag0 = A + (size_t)(m0 + r0) * IN_F + c0;
  const float* Ag1 = A + (size_t)(m0 + r1) * IN_F + c0;
  const float* Bg0 = B + (size_t)(n0 + r0) * IN_F + c0;
  const float* Bg1 = B + (size_t)(n0 + r1) * IN_F + c0;

  float acc[8][8];
#pragma unroll
  for (int i = 0; i < 8; i++)
#pragma unroll
    for (int j = 0; j < 8; j++) acc[i][j] = 0.0f;

  // Prologue prefetch (k0 = 0)
  float4 pa0 = *(const float4*)(Ag0);
  float4 pa1 = *(const float4*)(Ag1);
  float4 pb0 = *(const float4*)(Bg0);
  float4 pb1 = *(const float4*)(Bg1);

  for (int k0 = 0; k0 < IN_F; k0 += BK) {
    // Commit prefetched tile to smem (transposed to [k][row])
    As[c0 + 0][r0] = pa0.x; As[c0 + 1][r0] = pa0.y;
    As[c0 + 2][r0] = pa0.z; As[c0 + 3][r0] = pa0.w;
    As[c0 + 0][r1] = pa1.x; As[c0 + 1][r1] = pa1.y;
    As[c0 + 2][r1] = pa1.z; As[c0 + 3][r1] = pa1.w;
    Bs[c0 + 0][r0] = pb0.x; Bs[c0 + 1][r0] = pb0.y;
    Bs[c0 + 2][r0] = pb0.z; Bs[c0 + 3][r0] = pb0.w;
    Bs[c0 + 0][r1] = pb1.x; Bs[c0 + 1][r1] = pb1.y;
    Bs[c0 + 2][r1] = pb1.z; Bs[c0 + 3][r1] = pb1.w;
    __syncthreads();

    // Issue next tile's gmem loads (latency hidden by compute below)
    const int kn = k0 + BK;
    if (kn < IN_F) {
      pa0 = *(const float4*)(Ag0 + kn);
      pa1 = *(const float4*)(Ag1 + kn);
      pb0 = *(const float4*)(Bg0 + kn);
      pb1 = *(const float4*)(Bg1 + kn);
    }

#pragma unroll
    for (int kk = 0; kk < BK; kk++) {
      float a_r[8], b_r[8];
      *(float4*)&a_r[0] = *(const float4*)&As[kk][ty * 8];
      *(float4*)&a_r[4] = *(const float4*)&As[kk][ty * 8 + 4];
      *(float4*)&b_r[0] = *(const float4*)&Bs[kk][tx * 8];
      *(float4*)&b_r[4] = *(const float4*)&Bs[kk][tx * 8 + 4];
#pragma unroll
      for (int i = 0; i < 8; i++) {
#pragma unroll
        for (int j = 0; j < 8; j++) {
          acc[i][j] += a_r[i] * b_r[j];
        }
      }
    }
    __syncthreads();
  }

  // Epilogue: fully covers C, vectorized stores.
#pragma unroll
  for (int i = 0; i < 8; i++) {
    float* cp = C + (size_t)(m0 + ty * 8 + i) * OUT_F + n0 + tx * 8;
    *(float4*)(cp) = make_float4(acc[i][0], acc[i][1], acc[i][2], acc[i][3]);
    *(float4*)(cp + 4) = make_float4(acc[i][4], acc[i][5], acc[i][6], acc[i][7]);
  }
}

// ---------------------------------------------------------------------------
// Launch: inputs in metadata order: x (f32), qweight (i32), u (f32), vt (f32)
// ---------------------------------------------------------------------------
extern "C" void kernel_launch(void* const* d_in, const int* in_sizes, int n_in,
                              void* d_out, int out_size) {
  const float* x = (const float*)d_in[0];
  const int* qweight = (const int*)d_in[1];
  const float* u = (const float*)d_in[2];
  const float* vt = (const float*)d_in[3];
  float* y = (float*)d_out;

  (void)in_sizes; (void)n_in; (void)out_size;

  // 1) Reconstruct w into g_w
  dim3 rgrid(IN_F / 128, OUT_F / 32);  // (32, 344)
  reconstruct_kernel<<<rgrid, 256>>>(qweight, u, vt);

  // 2) y = x @ w^T
  dim3 ggrid(OUT_F / BN, TOKENS / BM);  // (86, 16)
  sgemm_kernel<<<ggrid, 256>>>(x, y);
}

// round 3
// speedup vs baseline: 3.5249x; 3.5249x over previous
#include <cuda_runtime.h>
#include <cuda_fp16.h>
#include <cstdint>

#define W_BIT 4
#define OUT_F 11008
#define IN_F 4096
#define KRANK 16
#define TOKENS 2048
#define NBYTES (OUT_F * IN_F / 8)

// fp16 staging buffers (static device globals: allocation-free rule)
__device__ __half g_w[(size_t)OUT_F * (size_t)IN_F];   // reconstructed weight, K-major
__device__ __half g_x[(size_t)TOKENS * (size_t)IN_F];  // x in fp16, K-major

// ---------------------------------------------------------------------------
// PTX helpers (baseline compute_103-safe: cp.async / ldmatrix / mma.sync only)
// ---------------------------------------------------------------------------
__device__ __forceinline__ uint32_t smem_u32(const void* p) {
  uint32_t a;
  asm("{ .reg .u64 t; cvta.to.shared.u64 t, %1; cvt.u32.u64 %0, t; }"
      : "=r"(a) : "l"(p));
  return a;
}

#define CP_ASYNC16(dst, src) \
  asm volatile("cp.async.cg.shared.global [%0], [%1], 16;" ::"r"(dst), "l"(src) : "memory")
#define CP_COMMIT() asm volatile("cp.async.commit_group;" ::: "memory")
#define CP_WAIT(n)  asm volatile("cp.async.wait_group %0;" ::"n"(n) : "memory")

#define LDSM_X4(r, addr)                                                  \
  asm volatile(                                                           \
      "ldmatrix.sync.aligned.m8n8.x4.shared.b16 {%0,%1,%2,%3}, [%4];"     \
      : "=r"((r)[0]), "=r"((r)[1]), "=r"((r)[2]), "=r"((r)[3])            \
      : "r"(addr))

#define MMA16816(d, a, b)                                                 \
  asm volatile(                                                           \
      "mma.sync.aligned.m16n8k16.row.col.f32.f16.f16.f32 "                \
      "{%0,%1,%2,%3}, {%4,%5,%6,%7}, {%8,%9}, {%0,%1,%2,%3};"             \
      : "+f"((d)[0]), "+f"((d)[1]), "+f"((d)[2]), "+f"((d)[3])            \
      : "r"((a)[0]), "r"((a)[1]), "r"((a)[2]), "r"((a)[3]),               \
        "r"((b)[0]), "r"((b)[1]))

// ---------------------------------------------------------------------------
// Kernel 0: x -> fp16
// ---------------------------------------------------------------------------
__global__ __launch_bounds__(256) void convert_x_kernel(const float* __restrict__ x) {
  size_t i = ((size_t)blockIdx.x * 256 + threadIdx.x) * 4;
  float4 v = *(const float4*)(x + i);
  __half2 h0 = __floats2half2_rn(v.x, v.y);
  __half2 h1 = __floats2half2_rn(v.z, v.w);
  uint2 p;
  p.x = *(const unsigned*)&h0;
  p.y = *(const unsigned*)&h1;
  *(uint2*)(g_x + i) = p;
}

// ---------------------------------------------------------------------------
// Kernel 1: reconstruct w[o][i] = sum_b sign * (u_b[o,:] . vt_b[:,i]) -> fp16
// Block: 256 threads = 32 o x 8 byte-groups, i-tile of 128. vt tile in smem.
// ---------------------------------------------------------------------------
__global__ __launch_bounds__(256) void reconstruct_kernel(
    const int* __restrict__ qweight, const float* __restrict__ u,
    const float* __restrict__ vt) {
  __shared__ __align__(16) float vts[W_BIT * KRANK][128];  // 32 KB

  const int tid = threadIdx.x;
  const int i_base = blockIdx.x * 128;

  // Cooperative vt tile load: 64 rows x 128 floats = 2048 float4 slots
#pragma unroll
  for (int j = 0; j < 8; j++) {
    int s = tid + j * 256;
    int rk = s >> 5;
    int c4 = (s & 31) << 2;
    *(float4*)&vts[rk][c4] =
        *(const float4*)(vt + (size_t)rk * IN_F + i_base + c4);
  }

  const int o = blockIdx.y * 32 + (tid >> 3);
  const int g = tid & 7;

  // u row in registers: u[b][o][k]
  float u_r[W_BIT * KRANK];
#pragma unroll
  for (int b = 0; b < W_BIT; b++) {
#pragma unroll
    for (int k4 = 0; k4 < KRANK / 4; k4++) {
      *(float4*)&u_r[b * KRANK + k4 * 4] =
          *(const float4*)(u + ((size_t)b * OUT_F + o) * KRANK + k4 * 4);
    }
  }
  __syncthreads();

#pragma unroll
  for (int gg = 0; gg < 2; gg++) {
    const int il = (g + gg * 8) * 8;  // local i offset, one byte = 8 elems
    const int i0 = i_base + il;
    float acc[8];
#pragma unroll
    for (int j = 0; j < 8; j++) acc[j] = 0.0f;

#pragma unroll
    for (int b = 0; b < W_BIT; b++) {
      const unsigned byte =
          (unsigned)qweight[b * NBYTES + o * (IN_F / 8) + (i0 >> 3)];
      float tmp[8];
#pragma unroll
      for (int j = 0; j < 8; j++) tmp[j] = 0.0f;
#pragma unroll
      for (int k = 0; k < KRANK; k++) {
        const float uv = u_r[b * KRANK + k];
        const float4 v0 = *(const float4*)&vts[b * KRANK + k][il];
        const float4 v1 = *(const float4*)&vts[b * KRANK + k][il + 4];
        tmp[0] += uv * v0.x; tmp[1] += uv * v0.y;
        tmp[2] += uv * v0.z; tmp[3] += uv * v0.w;
        tmp[4] += uv * v1.x; tmp[5] += uv * v1.y;
        tmp[6] += uv * v1.z; tmp[7] += uv * v1.w;
      }
#pragma unroll
      for (int j = 0; j < 8; j++)
        acc[j] += ((byte >> j) & 1u) ? tmp[j] : -tmp[j];
    }

    __half2 h0 = __floats2half2_rn(acc[0], acc[1]);
    __half2 h1 = __floats2half2_rn(acc[2], acc[3]);
    __half2 h2 = __floats2half2_rn(acc[4], acc[5]);
    __half2 h3 = __floats2half2_rn(acc[6], acc[7]);
    uint4 p;
    p.x = *(const unsigned*)&h0; p.y = *(const unsigned*)&h1;
    p.z = *(const unsigned*)&h2; p.w = *(const unsigned*)&h3;
    *(uint4*)(g_w + (size_t)o * IN_F + i0) = p;
  }
}

// ---------------------------------------------------------------------------
// Kernel 2: HMMA fp16 GEMM (mma.sync m16n8k16, fp32 accum)
// Y[T,O] = Xh[T,I] @ Wh[O,I]^T
// CTA tile 128x128, BK=64, 3-stage cp.async pipeline, 8 warps (2x4),
// warp tile 64x32. Smem rows padded to 144B (conflict-free ldmatrix).
// ---------------------------------------------------------------------------
#define BM 128
#define BN 128
#define BKK 64
#define GS 3
#define ROWB 144                      // 128B data + 16B pad per row
#define A_ST (BM * ROWB)              // 18432 B
#define B_ST (BN * ROWB)              // 18432 B
#define SMEM_TOTAL (GS * (A_ST + B_ST))  // 110592 B
#define NIT (IN_F / BKK)              // 64

__global__ __launch_bounds__(256, 1) void gemm_hmma_kernel(float* __restrict__ Y) {
  extern __shared__ char smem[];
  const uint32_t sb = smem_u32(smem);
  const int tid = threadIdx.x;
  const int wid = tid >> 5;
  const int lane = tid & 31;
  const int m0 = blockIdx.y * BM;
  const int n0 = blockIdx.x * BN;
  const int wm = wid & 1;   // 2 warp rows (M)
  const int wn = wid >> 1;  // 4 warp cols (N)

  const __half* Ag = g_x + (size_t)m0 * IN_F;
  const __half* Bg = g_w + (size_t)n0 * IN_F;

  // stage fill: A and B each 128 rows x 8 x 16B chunks = 1024 slots; 4/thread
  auto fill = [&](int s, int c) {
    const uint32_t ab = sb + s * A_ST;
    const uint32_t bb = sb + GS * A_ST + s * B_ST;
    const int k0 = c * BKK;
#pragma unroll
    for (int j = 0; j < 4; j++) {
      const int slot = tid + j * 256;
      const int row = slot >> 3, ch = slot & 7;
      CP_ASYNC16(ab + row * ROWB + ch * 16,
                 Ag + (size_t)row * IN_F + k0 + ch * 8);
      CP_ASYNC16(bb + row * ROWB + ch * 16,
                 Bg + (size_t)row * IN_F + k0 + ch * 8);
    }
    CP_COMMIT();
  };

  float acc[4][4][4];
#pragma unroll
  for (int mt = 0; mt < 4; mt++)
#pragma unroll
    for (int nt = 0; nt < 4; nt++)
#pragma unroll
      for (int q = 0; q < 4; q++) acc[mt][nt][q] = 0.0f;

  // prologue: fill stages 0..GS-2 with chunks 0..GS-2
#pragma unroll
  for (int p = 0; p < GS - 1; p++) fill(p, p);

  // precomputed ldmatrix lane offsets
  const int a_row_l = lane & 15;          // row within m16 tile
  const int a_ch_l = (lane >> 4) * 16;    // 16B chunk within k16
  const int b_g = lane >> 3;              // 0..3 matrix group
  const int b_row_l = ((b_g >> 1) * 8) + (lane & 7);  // row within n16 pair
  const int b_ch_l = (b_g & 1) * 16;      // chunk within k16

  for (int it = 0; it < NIT; it++) {
    CP_WAIT(GS - 2);
    __syncthreads();

    // refill the stage computed at it-1 with chunk it+GS-1 (keeps loads early)
    const int c = it + GS - 1;
    if (c < NIT) fill((it + GS - 1) % GS, c);
    else CP_COMMIT();  // uniform group accounting

    const int s = it % GS;
    const uint32_t ab = sb + s * A_ST;
    const uint32_t bb = sb + GS * A_ST + s * B_ST;

#pragma unroll
    for (int kt = 0; kt < BKK / 16; kt++) {
      uint32_t a[4][4];
#pragma unroll
      for (int mt = 0; mt < 4; mt++) {
        const uint32_t addr =
            ab + (wm * 64 + mt * 16 + a_row_l) * ROWB + kt * 32 + a_ch_l;
        LDSM_X4(a[mt], addr);
      }
      uint32_t b[4][2];
#pragma unroll
      for (int np = 0; np < 2; np++) {  // pairs of n8 tiles via one x4
        uint32_t r[4];
        const uint32_t addr =
            bb + (wn * 32 + np * 16 + b_row_l) * ROWB + kt * 32 + b_ch_l;
        LDSM_X4(r, addr);
        b[np * 2][0] = r[0]; b[np * 2][1] = r[1];
        b[np * 2 + 1][0] = r[2]; b[np * 2 + 1][1] = r[3];
      }
#pragma unroll
      for (int mt = 0; mt < 4; mt++)
#pragma unroll
        for (int nt = 0; nt < 4; nt++) MMA16816(acc[mt][nt], a[mt], b[nt]);
    }
    __syncthreads();
  }

  // epilogue: direct float2 stores per mma-tile fragment
#pragma unroll
  for (int mt = 0; mt < 4; mt++) {
#pragma unroll
    for (int nt = 0; nt < 4; nt++) {
      const int r = m0 + wm * 64 + mt * 16 + (lane >> 2);
      const int cc = n0 + wn * 32 + nt * 8 + (lane & 3) * 2;
      float2 v0 = make_float2(acc[mt][nt][0], acc[mt][nt][1]);
      float2 v1 = make_float2(acc[mt][nt][2], acc[mt][nt][3]);
      *(float2*)(Y + (size_t)r * OUT_F + cc) = v0;
      *(float2*)(Y + (size_t)(r + 8) * OUT_F + cc) = v1;
    }
  }
}

// ---------------------------------------------------------------------------
// Launch: inputs in metadata order: x (f32), qweight (i32), u (f32), vt (f32)
// ---------------------------------------------------------------------------
extern "C" void kernel_launch(void* const* d_in, const int* in_sizes, int n_in,
                              void* d_out, int out_size) {
  const float* x = (const float*)d_in[0];
  const int* qweight = (const int*)d_in[1];
  const float* u = (const float*)d_in[2];
  const float* vt = (const float*)d_in[3];
  float* y = (float*)d_out;
  (void)in_sizes; (void)n_in; (void)out_size;

  cudaFuncSetAttribute(gemm_hmma_kernel,
                       cudaFuncAttributeMaxDynamicSharedMemorySize, SMEM_TOTAL);

  // 0) x -> fp16
  convert_x_kernel<<<(TOKENS * IN_F) / (256 * 4), 256>>>(x);

  // 1) reconstruct w -> fp16
  dim3 rgrid(IN_F / 128, OUT_F / 32);  // (32, 344)
  reconstruct_kernel<<<rgrid, 256>>>(qweight, u, vt);

  // 2) HMMA GEMM
  dim3 ggrid(OUT_F / BN, TOKENS / BM);  // (86, 16)
  gemm_hmma_kernel<<<ggrid, 256, SMEM_TOTAL>>>(y);
}

// round 4
// speedup vs baseline: 3.8453x; 1.0909x over previous
#include <cuda_runtime.h>
#include <cuda_fp16.h>
#include <cstdint>

#define W_BIT 4
#define OUT_F 11008
#define IN_F 4096
#define KRANK 16
#define TOKENS 2048
#define NBYTES (OUT_F * IN_F / 8)

// fp16 staging buffers (static device globals: allocation-free rule)
__device__ __half g_w[(size_t)OUT_F * (size_t)IN_F];   // reconstructed weight, K-major
__device__ __half g_x[(size_t)TOKENS * (size_t)IN_F];  // x in fp16, K-major

// ---------------------------------------------------------------------------
// PTX helpers (baseline compute_103-safe: cp.async / ldmatrix / mma.sync only)
// ---------------------------------------------------------------------------
__device__ __forceinline__ uint32_t smem_u32(const void* p) {
  uint32_t a;
  asm("{ .reg .u64 t; cvta.to.shared.u64 t, %1; cvt.u32.u64 %0, t; }"
      : "=r"(a) : "l"(p));
  return a;
}

#define CP_ASYNC16(dst, src) \
  asm volatile("cp.async.cg.shared.global [%0], [%1], 16;" ::"r"(dst), "l"(src) : "memory")
#define CP_COMMIT() asm volatile("cp.async.commit_group;" ::: "memory")
#define CP_WAIT(n)  asm volatile("cp.async.wait_group %0;" ::"n"(n) : "memory")

#define LDSM_X4(r, addr)                                                  \
  asm volatile(                                                           \
      "ldmatrix.sync.aligned.m8n8.x4.shared.b16 {%0,%1,%2,%3}, [%4];"     \
      : "=r"((r)[0]), "=r"((r)[1]), "=r"((r)[2]), "=r"((r)[3])            \
      : "r"(addr))

#define MMA16816(d, a, b)                                                 \
  asm volatile(                                                           \
      "mma.sync.aligned.m16n8k16.row.col.f32.f16.f16.f32 "                \
      "{%0,%1,%2,%3}, {%4,%5,%6,%7}, {%8,%9}, {%0,%1,%2,%3};"             \
      : "+f"((d)[0]), "+f"((d)[1]), "+f"((d)[2]), "+f"((d)[3])            \
      : "r"((a)[0]), "r"((a)[1]), "r"((a)[2]), "r"((a)[3]),               \
        "r"((b)[0]), "r"((b)[1]))

// ---------------------------------------------------------------------------
// Kernel 0: x -> fp16
// ---------------------------------------------------------------------------
__global__ __launch_bounds__(256) void convert_x_kernel(const float* __restrict__ x) {
  size_t i = ((size_t)blockIdx.x * 256 + threadIdx.x) * 4;
  float4 v = *(const float4*)(x + i);
  __half2 h0 = __floats2half2_rn(v.x, v.y);
  __half2 h1 = __floats2half2_rn(v.z, v.w);
  uint2 p;
  p.x = *(const unsigned*)&h0;
  p.y = *(const unsigned*)&h1;
  *(uint2*)(g_x + i) = p;
}

// ---------------------------------------------------------------------------
// Kernel 1: reconstruct w[o][i] = sum_b sign * (u_b[o,:] . vt_b[:,i]) -> fp16
// Block: 256 threads = 32 o x 8 byte-groups, i-tile of 128. vt tile in smem.
// ---------------------------------------------------------------------------
__global__ __launch_bounds__(256) void reconstruct_kernel(
    const int* __restrict__ qweight, const float* __restrict__ u,
    const float* __restrict__ vt) {
  __shared__ __align__(16) float vts[W_BIT * KRANK][128];  // 32 KB

  const int tid = threadIdx.x;
  const int i_base = blockIdx.x * 128;

  // Cooperative vt tile load: 64 rows x 128 floats = 2048 float4 slots
#pragma unroll
  for (int j = 0; j < 8; j++) {
    int s = tid + j * 256;
    int rk = s >> 5;
    int c4 = (s & 31) << 2;
    *(float4*)&vts[rk][c4] =
        *(const float4*)(vt + (size_t)rk * IN_F + i_base + c4);
  }

  const int o = blockIdx.y * 32 + (tid >> 3);
  const int g = tid & 7;

  // u row in registers: u[b][o][k]
  float u_r[W_BIT * KRANK];
#pragma unroll
  for (int b = 0; b < W_BIT; b++) {
#pragma unroll
    for (int k4 = 0; k4 < KRANK / 4; k4++) {
      *(float4*)&u_r[b * KRANK + k4 * 4] =
          *(const float4*)(u + ((size_t)b * OUT_F + o) * KRANK + k4 * 4);
    }
  }
  __syncthreads();

#pragma unroll
  for (int gg = 0; gg < 2; gg++) {
    const int il = (g + gg * 8) * 8;  // local i offset, one byte = 8 elems
    const int i0 = i_base + il;
    float acc[8];
#pragma unroll
    for (int j = 0; j < 8; j++) acc[j] = 0.0f;

#pragma unroll
    for (int b = 0; b < W_BIT; b++) {
      const unsigned byte =
          (unsigned)qweight[b * NBYTES + o * (IN_F / 8) + (i0 >> 3)];
      float tmp[8];
#pragma unroll
      for (int j = 0; j < 8; j++) tmp[j] = 0.0f;
#pragma unroll
      for (int k = 0; k < KRANK; k++) {
        const float uv = u_r[b * KRANK + k];
        const float4 v0 = *(const float4*)&vts[b * KRANK + k][il];
        const float4 v1 = *(const float4*)&vts[b * KRANK + k][il + 4];
        tmp[0] += uv * v0.x; tmp[1] += uv * v0.y;
        tmp[2] += uv * v0.z; tmp[3] += uv * v0.w;
        tmp[4] += uv * v1.x; tmp[5] += uv * v1.y;
        tmp[6] += uv * v1.z; tmp[7] += uv * v1.w;
      }
#pragma unroll
      for (int j = 0; j < 8; j++)
        acc[j] += ((byte >> j) & 1u) ? tmp[j] : -tmp[j];
    }

    __half2 h0 = __floats2half2_rn(acc[0], acc[1]);
    __half2 h1 = __floats2half2_rn(acc[2], acc[3]);
    __half2 h2 = __floats2half2_rn(acc[4], acc[5]);
    __half2 h3 = __floats2half2_rn(acc[6], acc[7]);
    uint4 p;
    p.x = *(const unsigned*)&h0; p.y = *(const unsigned*)&h1;
    p.z = *(const unsigned*)&h2; p.w = *(const unsigned*)&h3;
    *(uint4*)(g_w + (size_t)o * IN_F + i0) = p;
  }
}

// ---------------------------------------------------------------------------
// Kernel 2: HMMA fp16 GEMM (mma.sync m16n8k16, fp32 accum)
// Y[T,O] = Xh[T,I] @ Wh[O,I]^T
// CTA tile 128x256, BK=64, 3-stage cp.async pipeline, 8 warps (2x4),
// warp tile 64x64 (MMA:LDSM = 32:8 per k16). Smem rows padded to 144B.
// ---------------------------------------------------------------------------
#define BM 128
#define BN 256
#define BKK 64
#define GS 3
#define ROWB 144                          // 128B data + 16B pad per row
#define A_ST (BM * ROWB)                  // 18432 B
#define B_ST (BN * ROWB)                  // 36864 B
#define SMEM_TOTAL (GS * (A_ST + B_ST))   // 165888 B
#define NIT (IN_F / BKK)                  // 64

__global__ __launch_bounds__(256, 1) void gemm_hmma_kernel(float* __restrict__ Y) {
  extern __shared__ char smem[];
  const uint32_t sb = smem_u32(smem);
  const int tid = threadIdx.x;
  const int wid = tid >> 5;
  const int lane = tid & 31;
  const int m0 = blockIdx.y * BM;
  const int n0 = blockIdx.x * BN;
  const int wm = wid & 1;   // 2 warp rows (M), 64 each
  const int wn = wid >> 1;  // 4 warp cols (N), 64 each

  const __half* Ag = g_x + (size_t)m0 * IN_F;
  const __half* Bg = g_w + (size_t)n0 * IN_F;

  // stage fill: A = 1024 slots of 16B (4/thread), B = 2048 slots (8/thread)
  auto fill = [&](int s, int c) {
    const uint32_t ab = sb + s * A_ST;
    const uint32_t bb = sb + GS * A_ST + s * B_ST;
    const int k0 = c * BKK;
#pragma unroll
    for (int j = 0; j < 4; j++) {
      const int slot = tid + j * 256;
      const int row = slot >> 3, ch = slot & 7;
      CP_ASYNC16(ab + row * ROWB + ch * 16,
                 Ag + (size_t)row * IN_F + k0 + ch * 8);
    }
#pragma unroll
    for (int j = 0; j < 8; j++) {
      const int slot = tid + j * 256;
      const int row = slot >> 3, ch = slot & 7;
      CP_ASYNC16(bb + row * ROWB + ch * 16,
                 Bg + (size_t)row * IN_F + k0 + ch * 8);
    }
    CP_COMMIT();
  };

  float acc[4][8][4];
#pragma unroll
  for (int mt = 0; mt < 4; mt++)
#pragma unroll
    for (int nt = 0; nt < 8; nt++)
#pragma unroll
      for (int q = 0; q < 4; q++) acc[mt][nt][q] = 0.0f;

  // prologue: fill stages 0..GS-2 with chunks 0..GS-2
#pragma unroll
  for (int p = 0; p < GS - 1; p++) fill(p, p);

  // ldmatrix lane offsets
  const int a_row_l = lane & 15;          // row within m16 tile
  const int a_ch_l = (lane >> 4) * 16;    // 16B chunk within k16
  const int b_g = lane >> 3;              // 0..3 matrix group
  const int b_row_l = ((b_g >> 1) * 8) + (lane & 7);  // row within n16 pair
  const int b_ch_l = (b_g & 1) * 16;      // chunk within k16

  for (int it = 0; it < NIT; it++) {
    CP_WAIT(GS - 2);
    __syncthreads();

    // refill the stage consumed at it-1 with chunk it+GS-1
    const int c = it + GS - 1;
    if (c < NIT) fill((it + GS - 1) % GS, c);
    else CP_COMMIT();  // uniform group accounting

    const int s = it % GS;
    const uint32_t ab = sb + s * A_ST;
    const uint32_t bb = sb + GS * A_ST + s * B_ST;

#pragma unroll
    for (int kt = 0; kt < BKK / 16; kt++) {
      uint32_t a[4][4];
#pragma unroll
      for (int mt = 0; mt < 4; mt++) {
        const uint32_t addr =
            ab + (wm * 64 + mt * 16 + a_row_l) * ROWB + kt * 32 + a_ch_l;
        LDSM_X4(a[mt], addr);
      }
      uint32_t b[8][2];
#pragma unroll
      for (int np = 0; np < 4; np++) {  // pairs of n8 tiles via one x4
        uint32_t r[4];
        const uint32_t addr =
            bb + (wn * 64 + np * 16 + b_row_l) * ROWB + kt * 32 + b_ch_l;
        LDSM_X4(r, addr);
        b[np * 2][0] = r[0]; b[np * 2][1] = r[1];
        b[np * 2 + 1][0] = r[2]; b[np * 2 + 1][1] = r[3];
      }
#pragma unroll
      for (int mt = 0; mt < 4; mt++)
#pragma unroll
        for (int nt = 0; nt < 8; nt++) MMA16816(acc[mt][nt], a[mt], b[nt]);
    }
    __syncthreads();
  }

  // epilogue: direct float2 stores per mma-tile fragment
#pragma unroll
  for (int mt = 0; mt < 4; mt++) {
#pragma unroll
    for (int nt = 0; nt < 8; nt++) {
      const int r = m0 + wm * 64 + mt * 16 + (lane >> 2);
      const int cc = n0 + wn * 64 + nt * 8 + (lane & 3) * 2;
      float2 v0 = make_float2(acc[mt][nt][0], acc[mt][nt][1]);
      float2 v1 = make_float2(acc[mt][nt][2], acc[mt][nt][3]);
      *(float2*)(Y + (size_t)r * OUT_F + cc) = v0;
      *(float2*)(Y + (size_t)(r + 8) * OUT_F + cc) = v1;
    }
  }
}

// ---------------------------------------------------------------------------
// Launch: inputs in metadata order: x (f32), qweight (i32), u (f32), vt (f32)
// ---------------------------------------------------------------------------
extern "C" void kernel_launch(void* const* d_in, const int* in_sizes, int n_in,
                              void* d_out, int out_size) {
  const float* x = (const float*)d_in[0];
  const int* qweight = (const int*)d_in[1];
  const float* u = (const float*)d_in[2];
  const float* vt = (const float*)d_in[3];
  float* y = (float*)d_out;
  (void)in_sizes; (void)n_in; (void)out_size;

  cudaFuncSetAttribute(gemm_hmma_kernel,
                       cudaFuncAttributeMaxDynamicSharedMemorySize, SMEM_TOTAL);

  // 0) x -> fp16
  convert_x_kernel<<<(TOKENS * IN_F) / (256 * 4), 256>>>(x);

  // 1) reconstruct w -> fp16
  dim3 rgrid(IN_F / 128, OUT_F / 32);  // (32, 344)
  reconstruct_kernel<<<rgrid, 256>>>(qweight, u, vt);

  // 2) HMMA GEMM
  dim3 ggrid(OUT_F / BN, TOKENS / BM);  // (43, 16)
  gemm_hmma_kernel<<<ggrid, 256, SMEM_TOTAL>>>(y);
}

// round 5
// speedup vs baseline: 5.9379x; 1.5442x over previous
#include <cuda_runtime.h>
#include <cuda_fp16.h>
#include <cstdint>

#define W_BIT 4
#define OUT_F 11008
#define IN_F 4096
#define KRANK 16
#define TOKENS 2048
#define NBYTES (OUT_F * IN_F / 8)

// fp16 staging buffers (static device globals: allocation-free rule)
__device__ __half g_w[(size_t)OUT_F * (size_t)IN_F];   // reconstructed weight, K-major
__device__ __half g_x[(size_t)TOKENS * (size_t)IN_F];  // x in fp16, K-major

// ---------------------------------------------------------------------------
// PTX helpers (baseline compute_103-safe: cp.async / ldmatrix / mma.sync only)
// ---------------------------------------------------------------------------
__device__ __forceinline__ uint32_t smem_u32(const void* p) {
  uint32_t a;
  asm("{ .reg .u64 t; cvta.to.shared.u64 t, %1; cvt.u32.u64 %0, t; }"
      : "=r"(a) : "l"(p));
  return a;
}

#define CP_ASYNC16(dst, src) \
  asm volatile("cp.async.cg.shared.global [%0], [%1], 16;" ::"r"(dst), "l"(src) : "memory")
#define CP_COMMIT() asm volatile("cp.async.commit_group;" ::: "memory")
#define CP_WAIT(n)  asm volatile("cp.async.wait_group %0;" ::"n"(n) : "memory")

#define LDSM_X4(r, addr)                                                  \
  asm volatile(                                                           \
      "ldmatrix.sync.aligned.m8n8.x4.shared.b16 {%0,%1,%2,%3}, [%4];"     \
      : "=r"((r)[0]), "=r"((r)[1]), "=r"((r)[2]), "=r"((r)[3])            \
      : "r"(addr))

#define MMA16816(d, a, b)                                                 \
  asm volatile(                                                           \
      "mma.sync.aligned.m16n8k16.row.col.f32.f16.f16.f32 "                \
      "{%0,%1,%2,%3}, {%4,%5,%6,%7}, {%8,%9}, {%0,%1,%2,%3};"             \
      : "+f"((d)[0]), "+f"((d)[1]), "+f"((d)[2]), "+f"((d)[3])            \
      : "r"((a)[0]), "r"((a)[1]), "r"((a)[2]), "r"((a)[3]),               \
        "r"((b)[0]), "r"((b)[1]))

// ---------------------------------------------------------------------------
// Kernel 0: x -> fp16
// ---------------------------------------------------------------------------
__global__ __launch_bounds__(256) void convert_x_kernel(const float* __restrict__ x) {
  size_t i = ((size_t)blockIdx.x * 256 + threadIdx.x) * 4;
  float4 v = *(const float4*)(x + i);
  __half2 h0 = __floats2half2_rn(v.x, v.y);
  __half2 h1 = __floats2half2_rn(v.z, v.w);
  uint2 p;
  p.x = *(const unsigned*)&h0;
  p.y = *(const unsigned*)&h1;
  *(uint2*)(g_x + i) = p;
}

// ---------------------------------------------------------------------------
// Kernel 1: reconstruct w -> fp16. Block tile: 64 o x 128 i, 256 threads.
// Each thread: 4 o x 8 i. vt tile and u tile staged in smem; vt float4
// loads amortized over the 4 o's (LDS/elem: 256B -> ~96B).
// ---------------------------------------------------------------------------
__global__ __launch_bounds__(256) void reconstruct_kernel(
    const int* __restrict__ qweight, const float* __restrict__ u,
    const float* __restrict__ vt) {
  __shared__ __align__(16) float vts[W_BIT * KRANK][128];  // 32 KB
  __shared__ __align__(16) float us[64][W_BIT * KRANK];    // 16 KB

  const int tid = threadIdx.x;
  const int i_base = blockIdx.x * 128;
  const int o_base = blockIdx.y * 64;

  // vt tile: 64 rows x 128 floats = 2048 float4 slots, 8 per thread
#pragma unroll
  for (int j = 0; j < 8; j++) {
    int s = tid + j * 256;
    int rk = s >> 5;
    int c4 = (s & 31) << 2;
    *(float4*)&vts[rk][c4] =
        *(const float4*)(vt + (size_t)rk * IN_F + i_base + c4);
  }

  // u tile: us[o_local][b*16+k] ; 64 o x 64 = 1024 float4 slots, 4 per thread
#pragma unroll
  for (int j = 0; j < 4; j++) {
    int s = tid + j * 256;
    int ol = s >> 4;        // 0..63
    int q = s & 15;         // 16 float4 per o
    int b = q >> 2, k4 = q & 3;
    *(float4*)&us[ol][b * KRANK + k4 * 4] =
        *(const float4*)(u + ((size_t)b * OUT_F + o_base + ol) * KRANK + k4 * 4);
  }
  __syncthreads();

  const int og = tid >> 4;        // 0..15 -> 4 o's each
  const int il = (tid & 15) * 8;  // 8 consecutive i

  float acc[4][8];
#pragma unroll
  for (int oo = 0; oo < 4; oo++)
#pragma unroll
    for (int j = 0; j < 8; j++) acc[oo][j] = 0.0f;

#pragma unroll
  for (int b = 0; b < W_BIT; b++) {
    float tmp[4][8];
#pragma unroll
    for (int oo = 0; oo < 4; oo++)
#pragma unroll
      for (int j = 0; j < 8; j++) tmp[oo][j] = 0.0f;

#pragma unroll
    for (int k4 = 0; k4 < 4; k4++) {
      float4 u4[4];
#pragma unroll
      for (int oo = 0; oo < 4; oo++)
        u4[oo] = *(const float4*)&us[og * 4 + oo][b * KRANK + k4 * 4];
#pragma unroll
      for (int kk = 0; kk < 4; kk++) {
        const int k = k4 * 4 + kk;
        const float4 v0 = *(const float4*)&vts[b * KRANK + k][il];
        const float4 v1 = *(const float4*)&vts[b * KRANK + k][il + 4];
#pragma unroll
        for (int oo = 0; oo < 4; oo++) {
          const float uv = (kk == 0) ? u4[oo].x
                          : (kk == 1) ? u4[oo].y
                          : (kk == 2) ? u4[oo].z : u4[oo].w;
          tmp[oo][0] += uv * v0.x; tmp[oo][1] += uv * v0.y;
          tmp[oo][2] += uv * v0.z; tmp[oo][3] += uv * v0.w;
          tmp[oo][4] += uv * v1.x; tmp[oo][5] += uv * v1.y;
          tmp[oo][6] += uv * v1.z; tmp[oo][7] += uv * v1.w;
        }
      }
    }

#pragma unroll
    for (int oo = 0; oo < 4; oo++) {
      const int o = o_base + og * 4 + oo;
      const unsigned byte =
          (unsigned)qweight[b * NBYTES + o * (IN_F / 8) + ((i_base + il) >> 3)];
#pragma unroll
      for (int j = 0; j < 8; j++)
        acc[oo][j] += ((byte >> j) & 1u) ? tmp[oo][j] : -tmp[oo][j];
    }
  }

#pragma unroll
  for (int oo = 0; oo < 4; oo++) {
    const int o = o_base + og * 4 + oo;
    __half2 h0 = __floats2half2_rn(acc[oo][0], acc[oo][1]);
    __half2 h1 = __floats2half2_rn(acc[oo][2], acc[oo][3]);
    __half2 h2 = __floats2half2_rn(acc[oo][4], acc[oo][5]);
    __half2 h3 = __floats2half2_rn(acc[oo][6], acc[oo][7]);
    uint4 p;
    p.x = *(const unsigned*)&h0; p.y = *(const unsigned*)&h1;
    p.z = *(const unsigned*)&h2; p.w = *(const unsigned*)&h3;
    *(uint4*)(g_w + (size_t)o * IN_F + i_base + il) = p;
  }
}

// ---------------------------------------------------------------------------
// Kernel 2: HMMA fp16 GEMM (mma.sync m16n8k16, fp32 accum)
// Y[T,O] = Xh[T,I] @ Wh[O,I]^T
// CTA tile 128x256, BK=64, 3-stage cp.async pipeline, 16 warps (4x4),
// warp tile 32x64 -> 4 warps/SMSP for latency hiding.
// ---------------------------------------------------------------------------
#define BM 128
#define BN 256
#define BKK 64
#define GS 3
#define ROWB 144                          // 128B data + 16B pad per row
#define A_ST (BM * ROWB)                  // 18432 B
#define B_ST (BN * ROWB)                  // 36864 B
#define SMEM_TOTAL (GS * (A_ST + B_ST))   // 165888 B
#define NIT (IN_F / BKK)                  // 64
#define NTHR 512

__global__ __launch_bounds__(NTHR, 1) void gemm_hmma_kernel(float* __restrict__ Y) {
  extern __shared__ char smem[];
  const uint32_t sb = smem_u32(smem);
  const int tid = threadIdx.x;
  const int wid = tid >> 5;
  const int lane = tid & 31;
  const int m0 = blockIdx.y * BM;
  const int n0 = blockIdx.x * BN;
  const int wm = wid & 3;   // 4 warp rows (M), 32 each
  const int wn = wid >> 2;  // 4 warp cols (N), 64 each

  const __half* Ag = g_x + (size_t)m0 * IN_F;
  const __half* Bg = g_w + (size_t)n0 * IN_F;

  // stage fill: A = 1024 slots of 16B (2/thread), B = 2048 slots (4/thread)
  auto fill = [&](int s, int c) {
    const uint32_t ab = sb + s * A_ST;
    const uint32_t bb = sb + GS * A_ST + s * B_ST;
    const int k0 = c * BKK;
#pragma unroll
    for (int j = 0; j < 2; j++) {
      const int slot = tid + j * NTHR;
      const int row = slot >> 3, ch = slot & 7;
      CP_ASYNC16(ab + row * ROWB + ch * 16,
                 Ag + (size_t)row * IN_F + k0 + ch * 8);
    }
#pragma unroll
    for (int j = 0; j < 4; j++) {
      const int slot = tid + j * NTHR;
      const int row = slot >> 3, ch = slot & 7;
      CP_ASYNC16(bb + row * ROWB + ch * 16,
                 Bg + (size_t)row * IN_F + k0 + ch * 8);
    }
    CP_COMMIT();
  };

  float acc[2][8][4];
#pragma unroll
  for (int mt = 0; mt < 2; mt++)
#pragma unroll
    for (int nt = 0; nt < 8; nt++)
#pragma unroll
      for (int q = 0; q < 4; q++) acc[mt][nt][q] = 0.0f;

  // prologue: fill stages 0..GS-2 with chunks 0..GS-2
#pragma unroll
  for (int p = 0; p < GS - 1; p++) fill(p, p);

  // ldmatrix lane offsets
  const int a_row_l = lane & 15;          // row within m16 tile
  const int a_ch_l = (lane >> 4) * 16;    // 16B chunk within k16
  const int b_g = lane >> 3;              // 0..3 matrix group
  const int b_row_l = ((b_g >> 1) * 8) + (lane & 7);  // row within n16 pair
  const int b_ch_l = (b_g & 1) * 16;      // chunk within k16

  for (int it = 0; it < NIT; it++) {
    CP_WAIT(GS - 2);
    __syncthreads();

    // refill the stage consumed at it-1 with chunk it+GS-1
    const int c = it + GS - 1;
    if (c < NIT) fill((it + GS - 1) % GS, c);
    else CP_COMMIT();  // uniform group accounting

    const int s = it % GS;
    const uint32_t ab = sb + s * A_ST;
    const uint32_t bb = sb + GS * A_ST + s * B_ST;

#pragma unroll
    for (int kt = 0; kt < BKK / 16; kt++) {
      uint32_t a[2][4];
#pragma unroll
      for (int mt = 0; mt < 2; mt++) {
        const uint32_t addr =
            ab + (wm * 32 + mt * 16 + a_row_l) * ROWB + kt * 32 + a_ch_l;
        LDSM_X4(a[mt], addr);
      }
      uint32_t b[8][2];
#pragma unroll
      for (int np = 0; np < 4; np++) {  // pairs of n8 tiles via one x4
        uint32_t r[4];
        const uint32_t addr =
            bb + (wn * 64 + np * 16 + b_row_l) * ROWB + kt * 32 + b_ch_l;
        LDSM_X4(r, addr);
        b[np * 2][0] = r[0]; b[np * 2][1] = r[1];
        b[np * 2 + 1][0] = r[2]; b[np * 2 + 1][1] = r[3];
      }
#pragma unroll
      for (int mt = 0; mt < 2; mt++)
#pragma unroll
        for (int nt = 0; nt < 8; nt++) MMA16816(acc[mt][nt], a[mt], b[nt]);
    }
    __syncthreads();
  }

  // epilogue: direct float2 stores per mma-tile fragment
#pragma unroll
  for (int mt = 0; mt < 2; mt++) {
#pragma unroll
    for (int nt = 0; nt < 8; nt++) {
      const int r = m0 + wm * 32 + mt * 16 + (lane >> 2);
      const int cc = n0 + wn * 64 + nt * 8 + (lane & 3) * 2;
      float2 v0 = make_float2(acc[mt][nt][0], acc[mt][nt][1]);
      float2 v1 = make_float2(acc[mt][nt][2], acc[mt][nt][3]);
      *(float2*)(Y + (size_t)r * OUT_F + cc) = v0;
      *(float2*)(Y + (size_t)(r + 8) * OUT_F + cc) = v1;
    }
  }
}

// ---------------------------------------------------------------------------
// Launch: inputs in metadata order: x (f32), qweight (i32), u (f32), vt (f32)
// ---------------------------------------------------------------------------
extern "C" void kernel_launch(void* const* d_in, const int* in_sizes, int n_in,
                              void* d_out, int out_size) {
  const float* x = (const float*)d_in[0];
  const int* qweight = (const int*)d_in[1];
  const float* u = (const float*)d_in[2];
  const float* vt = (const float*)d_in[3];
  float* y = (float*)d_out;
  (void)in_sizes; (void)n_in; (void)out_size;

  cudaFuncSetAttribute(gemm_hmma_kernel,
                       cudaFuncAttributeMaxDynamicSharedMemorySize, SMEM_TOTAL);

  // 0) x -> fp16
  convert_x_kernel<<<(TOKENS * IN_F) / (256 * 4), 256>>>(x);

  // 1) reconstruct w -> fp16 (64 o x 128 i per block)
  dim3 rgrid(IN_F / 128, OUT_F / 64);  // (32, 172)
  reconstruct_kernel<<<rgrid, 256>>>(qweight, u, vt);

  // 2) HMMA GEMM
  dim3 ggrid(OUT_F / BN, TOKENS / BM);  // (43, 16)
  gemm_hmma_kernel<<<ggrid, NTHR, SMEM_TOTAL>>>(y);
}

// round 6
// speedup vs baseline: 5.9625x; 1.0041x over previous
#include <cuda_runtime.h>
#include <cuda_fp16.h>
#include <cstdint>

#define W_BIT 4
#define OUT_F 11008
#define IN_F 4096
#define KRANK 16
#define TOKENS 2048
#define NBYTES (OUT_F * IN_F / 8)

// fp16 staging buffers (static device globals: allocation-free rule)
__device__ __half g_w[(size_t)OUT_F * (size_t)IN_F];   // reconstructed weight, K-major
__device__ __half g_x[(size_t)TOKENS * (size_t)IN_F];  // x in fp16, K-major

// ---------------------------------------------------------------------------
// PTX helpers (baseline compute_103-safe: cp.async / ldmatrix / mma.sync only)
// ---------------------------------------------------------------------------
__device__ __forceinline__ uint32_t smem_u32(const void* p) {
  uint32_t a;
  asm("{ .reg .u64 t; cvta.to.shared.u64 t, %1; cvt.u32.u64 %0, t; }"
      : "=r"(a) : "l"(p));
  return a;
}

#define CP_ASYNC16(dst, src) \
  asm volatile("cp.async.cg.shared.global [%0], [%1], 16;" ::"r"(dst), "l"(src) : "memory")
#define CP_COMMIT() asm volatile("cp.async.commit_group;" ::: "memory")
#define CP_WAIT(n)  asm volatile("cp.async.wait_group %0;" ::"n"(n) : "memory")

#define LDSM_X4(r, addr)                                                  \
  asm volatile(                                                           \
      "ldmatrix.sync.aligned.m8n8.x4.shared.b16 {%0,%1,%2,%3}, [%4];"     \
      : "=r"((r)[0]), "=r"((r)[1]), "=r"((r)[2]), "=r"((r)[3])            \
      : "r"(addr))

#define MMA16816(d, a, b)                                                 \
  asm volatile(                                                           \
      "mma.sync.aligned.m16n8k16.row.col.f32.f16.f16.f32 "                \
      "{%0,%1,%2,%3}, {%4,%5,%6,%7}, {%8,%9}, {%0,%1,%2,%3};"             \
      : "+f"((d)[0]), "+f"((d)[1]), "+f"((d)[2]), "+f"((d)[3])            \
      : "r"((a)[0]), "r"((a)[1]), "r"((a)[2]), "r"((a)[3]),               \
        "r"((b)[0]), "r"((b)[1]))

// ---------------------------------------------------------------------------
// Kernel 0: x -> fp16
// ---------------------------------------------------------------------------
__global__ __launch_bounds__(256) void convert_x_kernel(const float* __restrict__ x) {
  size_t i = ((size_t)blockIdx.x * 256 + threadIdx.x) * 4;
  float4 v = *(const float4*)(x + i);
  __half2 h0 = __floats2half2_rn(v.x, v.y);
  __half2 h1 = __floats2half2_rn(v.z, v.w);
  uint2 p;
  p.x = *(const unsigned*)&h0;
  p.y = *(const unsigned*)&h1;
  *(uint2*)(g_x + i) = p;
}

// ---------------------------------------------------------------------------
// Kernel 1: reconstruct w -> fp16. Block tile: 64 o x 128 i, 256 threads.
// Each thread: 4 o x 8 i. vt tile and u tile staged in smem.
// ---------------------------------------------------------------------------
__global__ __launch_bounds__(256) void reconstruct_kernel(
    const int* __restrict__ qweight, const float* __restrict__ u,
    const float* __restrict__ vt) {
  __shared__ __align__(16) float vts[W_BIT * KRANK][128];  // 32 KB
  __shared__ __align__(16) float us[64][W_BIT * KRANK];    // 16 KB

  const int tid = threadIdx.x;
  const int i_base = blockIdx.x * 128;
  const int o_base = blockIdx.y * 64;

  // vt tile: 64 rows x 128 floats = 2048 float4 slots, 8 per thread
#pragma unroll
  for (int j = 0; j < 8; j++) {
    int s = tid + j * 256;
    int rk = s >> 5;
    int c4 = (s & 31) << 2;
    *(float4*)&vts[rk][c4] =
        *(const float4*)(vt + (size_t)rk * IN_F + i_base + c4);
  }

  // u tile: us[o_local][b*16+k]; 1024 float4 slots, 4 per thread
#pragma unroll
  for (int j = 0; j < 4; j++) {
    int s = tid + j * 256;
    int ol = s >> 4;
    int q = s & 15;
    int b = q >> 2, k4 = q & 3;
    *(float4*)&us[ol][b * KRANK + k4 * 4] =
        *(const float4*)(u + ((size_t)b * OUT_F + o_base + ol) * KRANK + k4 * 4);
  }

  const int og = tid >> 4;        // 0..15 -> 4 o's each
  const int il = (tid & 15) * 8;  // 8 consecutive i

  // prefetch sign bytes early (independent of smem staging)
  unsigned bytes[W_BIT][4];
#pragma unroll
  for (int b = 0; b < W_BIT; b++)
#pragma unroll
    for (int oo = 0; oo < 4; oo++) {
      const int o = o_base + og * 4 + oo;
      bytes[b][oo] =
          (unsigned)qweight[b * NBYTES + o * (IN_F / 8) + ((i_base + il) >> 3)];
    }

  __syncthreads();

  float acc[4][8];
#pragma unroll
  for (int oo = 0; oo < 4; oo++)
#pragma unroll
    for (int j = 0; j < 8; j++) acc[oo][j] = 0.0f;

#pragma unroll
  for (int b = 0; b < W_BIT; b++) {
    float tmp[4][8];
#pragma unroll
    for (int oo = 0; oo < 4; oo++)
#pragma unroll
      for (int j = 0; j < 8; j++) tmp[oo][j] = 0.0f;

#pragma unroll
    for (int k4 = 0; k4 < 4; k4++) {
      float4 u4[4];
#pragma unroll
      for (int oo = 0; oo < 4; oo++)
        u4[oo] = *(const float4*)&us[og * 4 + oo][b * KRANK + k4 * 4];
#pragma unroll
      for (int kk = 0; kk < 4; kk++) {
        const int k = k4 * 4 + kk;
        const float4 v0 = *(const float4*)&vts[b * KRANK + k][il];
        const float4 v1 = *(const float4*)&vts[b * KRANK + k][il + 4];
#pragma unroll
        for (int oo = 0; oo < 4; oo++) {
          const float uv = (kk == 0) ? u4[oo].x
                          : (kk == 1) ? u4[oo].y
                          : (kk == 2) ? u4[oo].z : u4[oo].w;
          tmp[oo][0] += uv * v0.x; tmp[oo][1] += uv * v0.y;
          tmp[oo][2] += uv * v0.z; tmp[oo][3] += uv * v0.w;
          tmp[oo][4] += uv * v1.x; tmp[oo][5] += uv * v1.y;
          tmp[oo][6] += uv * v1.z; tmp[oo][7] += uv * v1.w;
        }
      }
    }

#pragma unroll
    for (int oo = 0; oo < 4; oo++) {
#pragma unroll
      for (int j = 0; j < 8; j++)
        acc[oo][j] += ((bytes[b][oo] >> j) & 1u) ? tmp[oo][j] : -tmp[oo][j];
    }
  }

#pragma unroll
  for (int oo = 0; oo < 4; oo++) {
    const int o = o_base + og * 4 + oo;
    __half2 h0 = __floats2half2_rn(acc[oo][0], acc[oo][1]);
    __half2 h1 = __floats2half2_rn(acc[oo][2], acc[oo][3]);
    __half2 h2 = __floats2half2_rn(acc[oo][4], acc[oo][5]);
    __half2 h3 = __floats2half2_rn(acc[oo][6], acc[oo][7]);
    uint4 p;
    p.x = *(const unsigned*)&h0; p.y = *(const unsigned*)&h1;
    p.z = *(const unsigned*)&h2; p.w = *(const unsigned*)&h3;
    *(uint4*)(g_w + (size_t)o * IN_F + i_base + il) = p;
  }
}

// ---------------------------------------------------------------------------
// Kernel 2: HMMA fp16 GEMM (mma.sync m16n8k16, fp32 accum)
// CTA 128x256, BK=64, GS=3 cp.async pipeline, 16 warps, warp tile 32x64.
// Single barrier per iteration; A fragments double-buffered.
// ---------------------------------------------------------------------------
#define BM 128
#define BN 256
#define BKK 64
#define GS 3
#define ROWB 144                          // 128B data + 16B pad per row
#define A_ST (BM * ROWB)                  // 18432 B
#define B_ST (BN * ROWB)                  // 36864 B
#define SMEM_TOTAL (GS * (A_ST + B_ST))   // 165888 B
#define NIT (IN_F / BKK)                  // 64
#define NTHR 512

__global__ __launch_bounds__(NTHR, 1) void gemm_hmma_kernel(float* __restrict__ Y) {
  extern __shared__ char smem[];
  const uint32_t sb = smem_u32(smem);
  const int tid = threadIdx.x;
  const int wid = tid >> 5;
  const int lane = tid & 31;
  const int m0 = blockIdx.y * BM;
  const int n0 = blockIdx.x * BN;
  const int wm = wid & 3;   // 4 warp rows (M), 32 each
  const int wn = wid >> 2;  // 4 warp cols (N), 64 each

  const __half* Ag = g_x + (size_t)m0 * IN_F;
  const __half* Bg = g_w + (size_t)n0 * IN_F;

  auto fill = [&](int s, int c) {
    const uint32_t ab = sb + s * A_ST;
    const uint32_t bb = sb + GS * A_ST + s * B_ST;
    const int k0 = c * BKK;
#pragma unroll
    for (int j = 0; j < 2; j++) {
      const int slot = tid + j * NTHR;
      const int row = slot >> 3, ch = slot & 7;
      CP_ASYNC16(ab + row * ROWB + ch * 16,
                 Ag + (size_t)row * IN_F + k0 + ch * 8);
    }
#pragma unroll
    for (int j = 0; j < 4; j++) {
      const int slot = tid + j * NTHR;
      const int row = slot >> 3, ch = slot & 7;
      CP_ASYNC16(bb + row * ROWB + ch * 16,
                 Bg + (size_t)row * IN_F + k0 + ch * 8);
    }
    CP_COMMIT();
  };

  float acc[2][8][4];
#pragma unroll
  for (int mt = 0; mt < 2; mt++)
#pragma unroll
    for (int nt = 0; nt < 8; nt++)
#pragma unroll
      for (int q = 0; q < 4; q++) acc[mt][nt][q] = 0.0f;

  // prologue: fill stages 0..GS-2 with chunks 0..GS-2
#pragma unroll
  for (int p = 0; p < GS - 1; p++) fill(p, p);

  // ldmatrix lane offsets
  const int a_row_l = lane & 15;
  const int a_ch_l = (lane >> 4) * 16;
  const int b_g = lane >> 3;
  const int b_row_l = ((b_g >> 1) * 8) + (lane & 7);
  const int b_ch_l = (b_g & 1) * 16;

  // per-warp base smem offsets (stage-independent parts)
  const uint32_t a_lane_off = (wm * 32 + a_row_l) * ROWB + a_ch_l;
  const uint32_t b_lane_off = (wn * 64 + b_row_l) * ROWB + b_ch_l;

  for (int it = 0; it < NIT; it++) {
    CP_WAIT(GS - 2);
    __syncthreads();  // single barrier: publishes stage it, protects overwrites

    const int c = it + GS - 1;
    if (c < NIT) fill(c % GS, c);

    const int s = it % GS;
    const uint32_t ab = sb + s * A_ST + a_lane_off;
    const uint32_t bb = sb + GS * A_ST + s * B_ST + b_lane_off;

    // A fragments double-buffered across kt; B loaded at top of each kt
    uint32_t a[2][2][4];
#pragma unroll
    for (int mt = 0; mt < 2; mt++) LDSM_X4(a[0][mt], ab + mt * 16 * ROWB);

#pragma unroll
    for (int kt = 0; kt < BKK / 16; kt++) {
      const int cur = kt & 1;
      uint32_t b[8][2];
#pragma unroll
      for (int np = 0; np < 4; np++) {
        uint32_t r[4];
        LDSM_X4(r, bb + np * 16 * ROWB + kt * 32);
        b[np * 2][0] = r[0]; b[np * 2][1] = r[1];
        b[np * 2 + 1][0] = r[2]; b[np * 2 + 1][1] = r[3];
      }
      if (kt < 3) {
#pragma unroll
        for (int mt = 0; mt < 2; mt++)
          LDSM_X4(a[cur ^ 1][mt], ab + mt * 16 * ROWB + (kt + 1) * 32);
      }
#pragma unroll
      for (int mt = 0; mt < 2; mt++)
#pragma unroll
        for (int nt = 0; nt < 8; nt++) MMA16816(acc[mt][nt], a[cur][mt], b[nt]);
    }
  }

  // epilogue
#pragma unroll
  for (int mt = 0; mt < 2; mt++) {
#pragma unroll
    for (int nt = 0; nt < 8; nt++) {
      const int r = m0 + wm * 32 + mt * 16 + (lane >> 2);
      const int cc = n0 + wn * 64 + nt * 8 + (lane & 3) * 2;
      float2 v0 = make_float2(acc[mt][nt][0], acc[mt][nt][1]);
      float2 v1 = make_float2(acc[mt][nt][2], acc[mt][nt][3]);
      *(float2*)(Y + (size_t)r * OUT_F + cc) = v0;
      *(float2*)(Y + (size_t)(r + 8) * OUT_F + cc) = v1;
    }
  }
}

// ---------------------------------------------------------------------------
// Launch: inputs in metadata order: x (f32), qweight (i32), u (f32), vt (f32)
// ---------------------------------------------------------------------------
extern "C" void kernel_launch(void* const* d_in, const int* in_sizes, int n_in,
                              void* d_out, int out_size) {
  const float* x = (const float*)d_in[0];
  const int* qweight = (const int*)d_in[1];
  const float* u = (const float*)d_in[2];
  const float* vt = (const float*)d_in[3];
  float* y = (float*)d_out;
  (void)in_sizes; (void)n_in; (void)out_size;

  cudaFuncSetAttribute(gemm_hmma_kernel,
                       cudaFuncAttributeMaxDynamicSharedMemorySize, SMEM_TOTAL);

  // 0) x -> fp16
  convert_x_kernel<<<(TOKENS * IN_F) / (256 * 4), 256>>>(x);

  // 1) reconstruct w -> fp16 (64 o x 128 i per block)
  dim3 rgrid(IN_F / 128, OUT_F / 64);  // (32, 172)
  reconstruct_kernel<<<rgrid, 256>>>(qweight, u, vt);

  // 2) HMMA GEMM
  dim3 ggrid(OUT_F / BN, TOKENS / BM);  // (43, 16)
  gemm_hmma_kernel<<<ggrid, NTHR, SMEM_TOTAL>>>(y);
}

// round 8
// speedup vs baseline: 6.9156x; 1.1598x over previous
#include <cuda_runtime.h>
#include <cuda_fp16.h>
#include <cstdint>

#define W_BIT 4
#define OUT_F 11008
#define IN_F 4096
#define KRANK 16
#define TOKENS 2048
#define NBYTES (OUT_F * IN_F / 8)

// fp16 staging buffers (static device globals: allocation-free rule)
__device__ __half g_w[(size_t)OUT_F * (size_t)IN_F];   // reconstructed weight, K-major
__device__ __half g_x[(size_t)TOKENS * (size_t)IN_F];  // x in fp16, K-major

// ---------------------------------------------------------------------------
// PTX helpers (baseline compute_103-safe: cp.async / ldmatrix / mma.sync only)
// ---------------------------------------------------------------------------
__device__ __forceinline__ uint32_t smem_u32(const void* p) {
  uint32_t a;
  asm("{ .reg .u64 t; cvta.to.shared.u64 t, %1; cvt.u32.u64 %0, t; }"
      : "=r"(a) : "l"(p));
  return a;
}

#define CP_ASYNC16(dst, src) \
  asm volatile("cp.async.cg.shared.global [%0], [%1], 16;" ::"r"(dst), "l"(src) : "memory")
#define CP_COMMIT() asm volatile("cp.async.commit_group;" ::: "memory")
#define CP_WAIT(n)  asm volatile("cp.async.wait_group %0;" ::"n"(n) : "memory")

#define LDSM_X4(r, addr)                                                  \
  asm volatile(                                                           \
      "ldmatrix.sync.aligned.m8n8.x4.shared.b16 {%0,%1,%2,%3}, [%4];"     \
      : "=r"((r)[0]), "=r"((r)[1]), "=r"((r)[2]), "=r"((r)[3])            \
      : "r"(addr))

#define LDSM_X4_T(r, addr)                                                \
  asm volatile(                                                           \
      "ldmatrix.sync.aligned.m8n8.x4.trans.shared.b16 {%0,%1,%2,%3}, [%4];" \
      : "=r"((r)[0]), "=r"((r)[1]), "=r"((r)[2]), "=r"((r)[3])            \
      : "r"(addr))

#define MMA16816(d, a, b)                                                 \
  asm volatile(                                                           \
      "mma.sync.aligned.m16n8k16.row.col.f32.f16.f16.f32 "                \
      "{%0,%1,%2,%3}, {%4,%5,%6,%7}, {%8,%9}, {%0,%1,%2,%3};"             \
      : "+f"((d)[0]), "+f"((d)[1]), "+f"((d)[2]), "+f"((d)[3])            \
      : "r"((a)[0]), "r"((a)[1]), "r"((a)[2]), "r"((a)[3]),               \
        "r"((b)[0]), "r"((b)[1]))

__device__ __forceinline__ float xor_sign(float p, unsigned s) {
  return __uint_as_float(__float_as_uint(p) ^ s);
}

// ---------------------------------------------------------------------------
// Kernel 0: x -> fp16
// ---------------------------------------------------------------------------
__global__ __launch_bounds__(256) void convert_x_kernel(const float* __restrict__ x) {
  size_t i = ((size_t)blockIdx.x * 256 + threadIdx.x) * 4;
  float4 v = *(const float4*)(x + i);
  __half2 h0 = __floats2half2_rn(v.x, v.y);
  __half2 h1 = __floats2half2_rn(v.z, v.w);
  uint2 p;
  p.x = *(const unsigned*)&h0;
  p.y = *(const unsigned*)&h1;
  *(uint2*)(g_x + i) = p;
}

// ---------------------------------------------------------------------------
// Kernel 1: HMMA reconstruct. CTA tile: 128 o x 128 i, 256 threads, 8 warps
// (2 M x 4 N), warp tile 64 o x 32 i. Per bit b: P_b = u_b @ vt_b via
// m16n8k16 (K=16 = one k-step), sign applied in registers (XOR trick),
// summed in fp32, packed to fp16.
//
// smem layout (dynamic):
//   US: us[b][o][k] fp16, o-row padded to 48 B   -> 4*128*48  = 24576 B
//   VT: vts[b][k][i] fp16, k-row padded to 272 B -> 4*16*272  = 17408 B
//   QS: qs[b][o][ib] bytes (ib = i_local/8)      -> 4*128*16  =  8192 B
// ---------------------------------------------------------------------------
#define US_OFF 0
#define US_BSTR (128 * 48)       // 6144 per bit
#define VT_OFF 24576
#define VT_BSTR (16 * 272)       // 4352 per bit
#define QS_OFF (24576 + 17408)   // 41984
#define RS_TOTAL (QS_OFF + 4 * 128 * 16)  // 50176 B

__global__ __launch_bounds__(256, 1) void reconstruct_hmma_kernel(
    const int* __restrict__ qweight, const float* __restrict__ u,
    const float* __restrict__ vt) {
  extern __shared__ char rs[];
  const uint32_t sb = smem_u32(rs);
  const int tid = threadIdx.x;
  const int lane = tid & 31;
  const int wid = tid >> 5;
  const int wm = wid & 1;   // 2 warp rows (o), 64 each
  const int wn = wid >> 1;  // 4 warp cols (i), 32 each
  const int i_base = blockIdx.x * 128;
  const int o_base = blockIdx.y * 128;

  // ---- cooperative staging: 2048 slots each for u / vt / qweight ----
#pragma unroll
  for (int j = 0; j < 8; j++) {
    const int s = tid + j * 256;          // 0..2047
    const int b = s >> 9;                 // 0..3
    const int rem = s & 511;

    {  // u: [b][o 0..127][k4 0..3] float4 -> 4 fp16
      const int o = rem >> 2, k4 = rem & 3;
      const float4 uf = *(const float4*)(
          u + ((size_t)b * OUT_F + o_base + o) * KRANK + k4 * 4);
      __half2 h0 = __floats2half2_rn(uf.x, uf.y);
      __half2 h1 = __floats2half2_rn(uf.z, uf.w);
      uint2 pk = make_uint2(*(const unsigned*)&h0, *(const unsigned*)&h1);
      *(uint2*)(rs + US_OFF + b * US_BSTR + o * 48 + k4 * 8) = pk;
    }
    {  // vt: [b][k 0..15][c 0..31] float4 -> 4 fp16
      const int k = rem >> 5, c4 = (rem & 31) * 4;
      const float4 vf = *(const float4*)(
          vt + ((size_t)b * KRANK + k) * IN_F + i_base + c4);
      __half2 h0 = __floats2half2_rn(vf.x, vf.y);
      __half2 h1 = __floats2half2_rn(vf.z, vf.w);
      uint2 pk = make_uint2(*(const unsigned*)&h0, *(const unsigned*)&h1);
      *(uint2*)(rs + VT_OFF + b * VT_BSTR + k * 272 + c4 * 2) = pk;
    }
    {  // qweight: [b][o][q4 0..3] int4 (4 byte-valued ints) -> packed u32
      // FIX (R7 bug): include this CTA's i-tile offset (i_base/8).
      const int o = rem >> 2, q4 = rem & 3;
      const int4 qi = *(const int4*)(
          qweight + (size_t)b * NBYTES + (size_t)(o_base + o) * (IN_F / 8) +
          (i_base >> 3) + q4 * 4);
      const unsigned pk = (unsigned)qi.x | ((unsigned)qi.y << 8) |
                          ((unsigned)qi.z << 16) | ((unsigned)qi.w << 24);
      *(unsigned*)(rs + QS_OFF + b * 2048 + o * 16 + q4 * 4) = pk;
    }
  }
  __syncthreads();

  // ---- compute ----
  float acc[4][4][4];  // [mt][nt][frag]
#pragma unroll
  for (int mt = 0; mt < 4; mt++)
#pragma unroll
    for (int nt = 0; nt < 4; nt++)
#pragma unroll
      for (int q = 0; q < 4; q++) acc[mt][nt][q] = 0.0f;

  const int j0 = (lane & 3) * 2;  // bit position of c0/c1 within sign byte
  const unsigned char* qsm = (const unsigned char*)(rs + QS_OFF);

#pragma unroll
  for (int b = 0; b < W_BIT; b++) {
    // A fragments: u rows [wm*64 + mt*16 + (lane&15)], 16B chunk (lane>>4)
    uint32_t af[4][4];
#pragma unroll
    for (int mt = 0; mt < 4; mt++) {
      const uint32_t addr = sb + US_OFF + b * US_BSTR +
                            (wm * 64 + mt * 16 + (lane & 15)) * 48 +
                            (lane >> 4) * 16;
      LDSM_X4(af[mt], addr);
    }
    // B fragments: ldmatrix.trans from vts[k][i]; one x4 covers 2 n-tiles
    uint32_t bf[4][2];
#pragma unroll
    for (int p = 0; p < 2; p++) {
      const int k_r = ((lane >> 3) & 1) * 8 + (lane & 7);
      const int n_off = wn * 32 + p * 16 + (lane >> 4) * 8;
      const uint32_t addr =
          sb + VT_OFF + b * VT_BSTR + k_r * 272 + n_off * 2;
      uint32_t r[4];
      LDSM_X4_T(r, addr);
      bf[p * 2][0] = r[0]; bf[p * 2][1] = r[1];
      bf[p * 2 + 1][0] = r[2]; bf[p * 2 + 1][1] = r[3];
    }

#pragma unroll
    for (int mt = 0; mt < 4; mt++) {
      float p4[4][4];
#pragma unroll
      for (int nt = 0; nt < 4; nt++) {
        p4[nt][0] = 0.0f; p4[nt][1] = 0.0f;
        p4[nt][2] = 0.0f; p4[nt][3] = 0.0f;
        MMA16816(p4[nt], af[mt], bf[nt]);
      }
      const int o_lo = wm * 64 + mt * 16 + (lane >> 2);  // CTA-local o
      const int o_hi = o_lo + 8;
#pragma unroll
      for (int nt = 0; nt < 4; nt++) {
        const int ib = wn * 4 + nt;
        const unsigned nb_lo = ~(unsigned)qsm[b * 2048 + o_lo * 16 + ib];
        const unsigned nb_hi = ~(unsigned)qsm[b * 2048 + o_hi * 16 + ib];
        acc[mt][nt][0] += xor_sign(p4[nt][0], ((nb_lo >> j0) << 31));
        acc[mt][nt][1] += xor_sign(p4[nt][1], ((nb_lo >> (j0 + 1)) << 31));
        acc[mt][nt][2] += xor_sign(p4[nt][2], ((nb_hi >> j0) << 31));
        acc[mt][nt][3] += xor_sign(p4[nt][3], ((nb_hi >> (j0 + 1)) << 31));
      }
    }
  }

  // ---- store w fragments as fp16 (half2 per row pair) ----
#pragma unroll
  for (int mt = 0; mt < 4; mt++) {
    const int o_lo = o_base + wm * 64 + mt * 16 + (lane >> 2);
#pragma unroll
    for (int nt = 0; nt < 4; nt++) {
      const int i0 = i_base + wn * 32 + nt * 8 + j0;
      __half2 hlo = __floats2half2_rn(acc[mt][nt][0], acc[mt][nt][1]);
      __half2 hhi = __floats2half2_rn(acc[mt][nt][2], acc[mt][nt][3]);
      *(unsigned*)(g_w + (size_t)o_lo * IN_F + i0) = *(const unsigned*)&hlo;
      *(unsigned*)(g_w + (size_t)(o_lo + 8) * IN_F + i0) = *(const unsigned*)&hhi;
    }
  }
}

// ---------------------------------------------------------------------------
// Kernel 2: HMMA fp16 GEMM (unchanged — at HMMA roofline)
// CTA 128x256, BK=64, GS=3 cp.async pipeline, 16 warps, warp tile 32x64.
// ---------------------------------------------------------------------------
#define BM 128
#define BN 256
#define BKK 64
#define GS 3
#define ROWB 144
#define A_ST (BM * ROWB)
#define B_ST (BN * ROWB)
#define SMEM_TOTAL (GS * (A_ST + B_ST))
#define NIT (IN_F / BKK)
#define NTHR 512

__global__ __launch_bounds__(NTHR, 1) void gemm_hmma_kernel(float* __restrict__ Y) {
  extern __shared__ char smem[];
  const uint32_t sb = smem_u32(smem);
  const int tid = threadIdx.x;
  const int wid = tid >> 5;
  const int lane = tid & 31;
  const int m0 = blockIdx.y * BM;
  const int n0 = blockIdx.x * BN;
  const int wm = wid & 3;
  const int wn = wid >> 2;

  const __half* Ag = g_x + (size_t)m0 * IN_F;
  const __half* Bg = g_w + (size_t)n0 * IN_F;

  auto fill = [&](int s, int c) {
    const uint32_t ab = sb + s * A_ST;
    const uint32_t bb = sb + GS * A_ST + s * B_ST;
    const int k0 = c * BKK;
#pragma unroll
    for (int j = 0; j < 2; j++) {
      const int slot = tid + j * NTHR;
      const int row = slot >> 3, ch = slot & 7;
      CP_ASYNC16(ab + row * ROWB + ch * 16,
                 Ag + (size_t)row * IN_F + k0 + ch * 8);
    }
#pragma unroll
    for (int j = 0; j < 4; j++) {
      const int slot = tid + j * NTHR;
      const int row = slot >> 3, ch = slot & 7;
      CP_ASYNC16(bb + row * ROWB + ch * 16,
                 Bg + (size_t)row * IN_F + k0 + ch * 8);
    }
    CP_COMMIT();
  };

  float acc[2][8][4];
#pragma unroll
  for (int mt = 0; mt < 2; mt++)
#pragma unroll
    for (int nt = 0; nt < 8; nt++)
#pragma unroll
      for (int q = 0; q < 4; q++) acc[mt][nt][q] = 0.0f;

#pragma unroll
  for (int p = 0; p < GS - 1; p++) fill(p, p);

  const int a_row_l = lane & 15;
  const int a_ch_l = (lane >> 4) * 16;
  const int b_g = lane >> 3;
  const int b_row_l = ((b_g >> 1) * 8) + (lane & 7);
  const int b_ch_l = (b_g & 1) * 16;

  const uint32_t a_lane_off = (wm * 32 + a_row_l) * ROWB + a_ch_l;
  const uint32_t b_lane_off = (wn * 64 + b_row_l) * ROWB + b_ch_l;

  for (int it = 0; it < NIT; it++) {
    CP_WAIT(GS - 2);
    __syncthreads();

    const int c = it + GS - 1;
    if (c < NIT) fill(c % GS, c);

    const int s = it % GS;
    const uint32_t ab = sb + s * A_ST + a_lane_off;
    const uint32_t bb = sb + GS * A_ST + s * B_ST + b_lane_off;

    uint32_t a[2][2][4];
#pragma unroll
    for (int mt = 0; mt < 2; mt++) LDSM_X4(a[0][mt], ab + mt * 16 * ROWB);

#pragma unroll
    for (int kt = 0; kt < BKK / 16; kt++) {
      const int cur = kt & 1;
      uint32_t b[8][2];
#pragma unroll
      for (int np = 0; np < 4; np++) {
        uint32_t r[4];
        LDSM_X4(r, bb + np * 16 * ROWB + kt * 32);
        b[np * 2][0] = r[0]; b[np * 2][1] = r[1];
        b[np * 2 + 1][0] = r[2]; b[np * 2 + 1][1] = r[3];
      }
      if (kt < 3) {
#pragma unroll
        for (int mt = 0; mt < 2; mt++)
          LDSM_X4(a[cur ^ 1][mt], ab + mt * 16 * ROWB + (kt + 1) * 32);
      }
#pragma unroll
      for (int mt = 0; mt < 2; mt++)
#pragma unroll
        for (int nt = 0; nt < 8; nt++) MMA16816(acc[mt][nt], a[cur][mt], b[nt]);
    }
  }

#pragma unroll
  for (int mt = 0; mt < 2; mt++) {
#pragma unroll
    for (int nt = 0; nt < 8; nt++) {
      const int r = m0 + wm * 32 + mt * 16 + (lane >> 2);
      const int cc = n0 + wn * 64 + nt * 8 + (lane & 3) * 2;
      float2 v0 = make_float2(acc[mt][nt][0], acc[mt][nt][1]);
      float2 v1 = make_float2(acc[mt][nt][2], acc[mt][nt][3]);
      *(float2*)(Y + (size_t)r * OUT_F + cc) = v0;
      *(float2*)(Y + (size_t)(r + 8) * OUT_F + cc) = v1;
    }
  }
}

// ---------------------------------------------------------------------------
// Launch: inputs in metadata order: x (f32), qweight (i32), u (f32), vt (f32)
// ---------------------------------------------------------------------------
extern "C" void kernel_launch(void* const* d_in, const int* in_sizes, int n_in,
                              void* d_out, int out_size) {
  const float* x = (const float*)d_in[0];
  const int* qweight = (const int*)d_in[1];
  const float* u = (const float*)d_in[2];
  const float* vt = (const float*)d_in[3];
  float* y = (float*)d_out;
  (void)in_sizes; (void)n_in; (void)out_size;

  cudaFuncSetAttribute(gemm_hmma_kernel,
                       cudaFuncAttributeMaxDynamicSharedMemorySize, SMEM_TOTAL);
  cudaFuncSetAttribute(reconstruct_hmma_kernel,
                       cudaFuncAttributeMaxDynamicSharedMemorySize, RS_TOTAL);

  // 0) x -> fp16
  convert_x_kernel<<<(TOKENS * IN_F) / (256 * 4), 256>>>(x);

  // 1) HMMA reconstruct w -> fp16 (128 o x 128 i per CTA)
  dim3 rgrid(IN_F / 128, OUT_F / 128);  // (32, 86)
  reconstruct_hmma_kernel<<<rgrid, 256, RS_TOTAL>>>(qweight, u, vt);

  // 2) HMMA GEMM
  dim3 ggrid(OUT_F / BN, TOKENS / BM);  // (43, 16)
  gemm_hmma_kernel<<<ggrid, NTHR, SMEM_TOTAL>>>(y);
}